// round 3
// baseline (speedup 1.0000x reference)
#include <cuda_runtime.h>
#include <cstdint>

// ---------------------------------------------------------------------------
// Char-LSTM, 1024 steps, BATCH=512, UNITS=256, fp32 exact.
//
// Layout: 16 clusters x 8 CTAs (grid=128, 256 thr/CTA, 1 CTA/SM).
//   cluster  -> 32 batches
//   CTA rank -> 32 units => 128 gate columns (i|j|f|o blocks of 32)
// W_h slice (256 x 128 fp32 = 128KB) lives in SMEM for the whole run.
// h state (32 batches x 256 units, packed as batch-pairs for fma.rn.f32x2)
// is double-buffered in SMEM; each CTA pushes its 32-unit h slice to all 8
// cluster CTAs via st.shared::cluster each step; one barrier.cluster/step.
// ---------------------------------------------------------------------------

namespace {
constexpr int kSeq     = 1024;
constexpr int kThreads = 256;

// shared memory map (bytes)
constexpr uint32_t W_OFF   = 0;                   // 256 x 128 fp32
constexpr uint32_t W_BYTES = 256u * 128u * 4u;    // 131072
constexpr uint32_t H0_OFF  = W_OFF + W_BYTES;     // 131072
constexpr uint32_t H_BYTES = 256u * 16u * 8u;     // 32768 : [unit 0..255][pair 0..15] float2
constexpr uint32_t H1_OFF  = H0_OFF + H_BYTES;    // 163840
constexpr uint32_t H_XOR   = H0_OFF ^ H1_OFF;     // 0x8000
constexpr uint32_t G_OFF   = H1_OFF + H_BYTES;    // 196608 : gates [pair 0..15][col 0..127] float2
constexpr uint32_t G_BYTES = 16u * 128u * 8u;     // 16384
constexpr uint32_t TOK_OFF = G_OFF + G_BYTES;     // 212992 : 2 x 32 int (double-buffered tokens)
constexpr uint32_t SMEM_BYTES = TOK_OFF + 2u * 32u * 4u;  // 213248
}  // namespace

__device__ __forceinline__ uint32_t smem_u32(const void* p) {
    uint32_t a;
    asm("{ .reg .u64 t; cvta.to.shared.u64 t, %1; cvt.u32.u64 %0, t; }"
        : "=r"(a) : "l"(p));
    return a;
}

__device__ __forceinline__ uint32_t mapa_u32(uint32_t laddr, uint32_t rank) {
    uint32_t r;
    asm("mapa.shared::cluster.u32 %0, %1, %2;" : "=r"(r) : "r"(laddr), "r"(rank));
    return r;
}

__device__ __forceinline__ void st_cluster_f2(uint32_t addr, float2 v) {
    asm volatile("st.shared::cluster.v2.f32 [%0], {%1, %2};"
                 :: "r"(addr), "f"(v.x), "f"(v.y) : "memory");
}

__device__ __forceinline__ void cluster_sync_() {
    asm volatile("barrier.cluster.arrive.aligned;" ::: "memory");
    asm volatile("barrier.cluster.wait.aligned;" ::: "memory");
}

__device__ __forceinline__ uint32_t cta_rank_() {
    uint32_t r;
    asm("mov.u32 %0, %%cluster_ctarank;" : "=r"(r));
    return r;
}

// sigmoid / tanh via MUFU (__expf). Saturates cleanly for large |x|.
__device__ __forceinline__ float sigf(float x) {
    return __fdividef(1.0f, 1.0f + __expf(-x));
}
__device__ __forceinline__ float tanhf_(float x) {
    return 2.0f * sigf(2.0f * x) - 1.0f;
}

extern __shared__ char smem_raw[];

__global__ __launch_bounds__(kThreads, 1) __cluster_dims__(8, 1, 1)
void lstm_persistent_kernel(const int*   __restrict__ tokens,   // [512,1024]
                            const float* __restrict__ Wx,       // [128,1024]
                            const float* __restrict__ Wh,       // [256,1024]
                            const float* __restrict__ bias,     // [1024]
                            const float* __restrict__ Wd,       // [256,128]
                            const float* __restrict__ bd,       // [128]
                            float*       __restrict__ out)      // [512,128]
{
    const int tid = threadIdx.x;
    const uint32_t rank = cta_rank_();
    const int cluster_id = blockIdx.x >> 3;
    const int bbase = cluster_id * 32;        // first batch of this cluster

    float* w_s = reinterpret_cast<float*>(smem_raw + W_OFF);
    int*  tok0 = reinterpret_cast<int*>(smem_raw + TOK_OFF);
    int*  tok1 = tok0 + 32;

    // ---- load W_h slice into SMEM (once) -------------------------------
    // local col c: gate g = c>>5, unit u = c&31 -> global col g*256 + rank*32 + u
    for (int idx = tid; idx < 256 * 128; idx += kThreads) {
        int k = idx >> 7, c = idx & 127;
        int gcol = ((c >> 5) << 8) + (int)rank * 32 + (c & 31);
        w_s[idx] = Wh[k * 1024 + gcol];
    }
    // zero both h buffers
    {
        float2* h0 = reinterpret_cast<float2*>(smem_raw + H0_OFF);
        float2* h1 = reinterpret_cast<float2*>(smem_raw + H1_OFF);
        for (int i = tid; i < 256 * 16; i += kThreads) {
            h0[i] = make_float2(0.f, 0.f);
            h1[i] = make_float2(0.f, 0.f);
        }
    }

    // ---- per-thread constants -------------------------------------------
    // gemv role: col c = tid & 127 ; pair-half ph = tid >> 7 (pairs 8ph..8ph+7)
    const int c  = tid & 127;
    const int ph = tid >> 7;
    const int gcol_t = ((c >> 5) << 8) + (int)rank * 32 + (c & 31);
    const float bias_c = bias[gcol_t];

    // cell role: unit u_l = tid>>3 (0..31), pairs p0, p0+1 with p0 = 2*(tid&7)
    const int u_l = tid >> 3;
    const int p0  = (tid & 7) * 2;
    const int ug  = (int)rank * 32 + u_l;     // global unit index
    float2 cst[2] = { make_float2(0.f, 0.f), make_float2(0.f, 0.f) };

    // peer SMEM bases (DSMEM window) for the h exchange
    const uint32_t my_base = smem_u32(smem_raw);
    uint32_t peer_base[8];
#pragma unroll
    for (int r = 0; r < 8; ++r) peer_base[r] = mapa_u32(my_base, (uint32_t)r);

    // tokens for t=0
    if (tid < 32) tok0[tid] = tokens[(bbase + tid) * kSeq + 0];

    cluster_sync_();   // weights + zeroed h + tok0 visible cluster-wide

    uint32_t cur_off = H0_OFF;   // read buffer this step
    uint32_t nxt_off = H1_OFF;   // write buffer this step

    for (int t = 0; t < kSeq; ++t) {
        const int* tokc = (t & 1) ? tok1 : tok0;
        // prefetch next step's tokens (hidden behind the gemv)
        if (tid < 32 && t + 1 < kSeq) {
            int* tokn = (t & 1) ? tok0 : tok1;
            tokn[tid] = tokens[(bbase + tid) * kSeq + (t + 1)];
        }

        // prefetch W_x gather for this step's 16 batches of this thread's column
        float wx_lo[8], wx_hi[8];
#pragma unroll
        for (int j = 0; j < 8; ++j) {
            int p = 8 * ph + j;
            int t0 = tokc[2 * p];
            int t1 = tokc[2 * p + 1];
            wx_lo[j] = Wx[t0 * 1024 + gcol_t];
            wx_hi[j] = Wx[t1 * 1024 + gcol_t];
        }

        // ---- gemv: acc[pair] (+)= h[pair][k] * W[k][c], packed f32x2 ----
        unsigned long long acc[8];
#pragma unroll
        for (int j = 0; j < 8; ++j) acc[j] = 0ull;

        const char* hbase = smem_raw + cur_off + (uint32_t)ph * 64u;
#pragma unroll 2
        for (int k = 0; k < 256; ++k) {
            float w = w_s[(k << 7) + c];
            unsigned long long wp;
            asm("mov.b64 %0, {%1, %1};" : "=l"(wp) : "r"(__float_as_uint(w)));
            const ulonglong2* hk =
                reinterpret_cast<const ulonglong2*>(hbase + (uint32_t)k * 128u);
#pragma unroll
            for (int j2 = 0; j2 < 4; ++j2) {
                ulonglong2 hv = hk[j2];
                asm("fma.rn.f32x2 %0, %1, %2, %0;"
                    : "+l"(acc[2 * j2]) : "l"(hv.x), "l"(wp));
                asm("fma.rn.f32x2 %0, %1, %2, %0;"
                    : "+l"(acc[2 * j2 + 1]) : "l"(hv.y), "l"(wp));
            }
        }

        // ---- write gates (+ Wx + bias) to SMEM: g[pair][col] -------------
        {
            float2* g2w = reinterpret_cast<float2*>(smem_raw + G_OFF);
#pragma unroll
            for (int j = 0; j < 8; ++j) {
                int p = 8 * ph + j;
                float lo = __uint_as_float((uint32_t)acc[j]) + wx_lo[j] + bias_c;
                float hi = __uint_as_float((uint32_t)(acc[j] >> 32)) + wx_hi[j] + bias_c;
                g2w[p * 128 + c] = make_float2(lo, hi);
            }
        }
        __syncthreads();

        // ---- LSTM cell + h exchange to all 8 cluster CTAs ----------------
        {
            const float2* g2 = reinterpret_cast<const float2*>(smem_raw + G_OFF);
#pragma unroll
            for (int q = 0; q < 2; ++q) {
                int p = p0 + q;
                float2 gi = g2[p * 128 + u_l];          // i block
                float2 gj = g2[p * 128 + 32 + u_l];     // j block
                float2 gf = g2[p * 128 + 64 + u_l];     // f block
                float2 go = g2[p * 128 + 96 + u_l];     // o block
                float cx = cst[q].x * sigf(gf.x + 1.0f) + sigf(gi.x) * tanhf_(gj.x);
                float cy = cst[q].y * sigf(gf.y + 1.0f) + sigf(gi.y) * tanhf_(gj.y);
                cst[q].x = cx;
                cst[q].y = cy;
                float2 hh = make_float2(tanhf_(cx) * sigf(go.x),
                                        tanhf_(cy) * sigf(go.y));
                uint32_t off = nxt_off + (uint32_t)((ug * 16 + p) * 8);
#pragma unroll
                for (int r = 0; r < 8; ++r) st_cluster_f2(peer_base[r] + off, hh);
            }
        }

        cluster_sync_();           // h(next) complete everywhere; buffers swap
        cur_off ^= H_XOR;
        nxt_off ^= H_XOR;
    }

    // ---- final dense: out[b, :] = h[b] @ W_dense + b_dense ---------------
    // every CTA holds the full final h for its cluster's 32 batches in SMEM.
    // rank r emits output columns [16r, 16r+16); thread -> (col, 2 batches).
    {
        const float* hf = reinterpret_cast<const float*>(smem_raw + cur_off);
        int colr = (int)rank * 16 + (tid & 15);
        int b0 = tid >> 4;                      // 0..15
        float a0 = bd[colr];
        float a1 = a0;
#pragma unroll 8
        for (int k = 0; k < 256; ++k) {
            float wv = Wd[(k << 7) + colr];
            a0 += hf[(k << 5) + b0] * wv;
            a1 += hf[(k << 5) + b0 + 16] * wv;
        }
        out[(bbase + b0) * 128 + colr] = a0;
        out[(bbase + b0 + 16) * 128 + colr] = a1;
    }
}

extern "C" void kernel_launch(void* const* d_in, const int* in_sizes, int n_in,
                              void* d_out, int out_size) {
    (void)in_sizes; (void)n_in; (void)out_size;
    const int*   tokens = (const int*)d_in[0];
    const float* Wx     = (const float*)d_in[1];
    const float* Wh     = (const float*)d_in[2];
    const float* b      = (const float*)d_in[3];
    const float* Wd     = (const float*)d_in[4];
    const float* bd     = (const float*)d_in[5];
    float* out = (float*)d_out;

    cudaFuncSetAttribute(lstm_persistent_kernel,
                         cudaFuncAttributeMaxDynamicSharedMemorySize,
                         (int)SMEM_BYTES);

    // 16 clusters of 8 CTAs (static __cluster_dims__), 1 CTA/SM.
    lstm_persistent_kernel<<<128, kThreads, SMEM_BYTES>>>(
        tokens, Wx, Wh, b, Wd, bd, out);
}

// round 4
// speedup vs baseline: 1.1662x; 1.1662x over previous
#include <cuda_runtime.h>
#include <cstdint>

// ---------------------------------------------------------------------------
// Char-LSTM, 1024 steps, BATCH=512, UNITS=256, fp32 exact.
//
// 16 clusters x 8 CTAs (grid=128), 512 threads/CTA (16 warps, 1 CTA/SM).
//   cluster  -> 32 batches
//   CTA rank -> 32 units => 128 gate columns (i|j|f|o blocks of 32)
// W_h slice (256x128 fp32 = 128KB) SMEM-resident.
// Gemv thread: 1 column x 4 batch-pairs, packed fma.rn.f32x2 accumulators.
// Cell thread: 1 (unit, batch-pair); h broadcast to 8 cluster CTAs via
// st.shared::cluster into double-buffered h; one barrier.cluster per step.
// ---------------------------------------------------------------------------

namespace {
constexpr int kSeq     = 1024;
constexpr int kThreads = 512;

// shared memory map (bytes)
constexpr uint32_t W_OFF    = 0;                    // 256 x 128 fp32
constexpr uint32_t W_BYTES  = 256u * 128u * 4u;     // 131072
constexpr uint32_t H0_OFF   = W_OFF + W_BYTES;      // 131072
constexpr uint32_t H_BYTES  = 256u * 16u * 8u;      // 32768 : [k][pair] float2
constexpr uint32_t H1_OFF   = H0_OFF + H_BYTES;     // 163840
constexpr uint32_t H_XOR    = H0_OFF ^ H1_OFF;      // 0x8000
constexpr uint32_t G_OFF    = H1_OFF + H_BYTES;     // 196608
constexpr uint32_t G_STRIDE = 17;                   // float2 per column row (pad)
constexpr uint32_t G_BYTES  = 128u * G_STRIDE * 8u; // 17408
constexpr uint32_t TOK_OFF  = G_OFF + G_BYTES;      // 214016 : 2 x 32 int
constexpr uint32_t SMEM_BYTES = TOK_OFF + 2u * 32u * 4u;  // 214272
}  // namespace

__device__ __forceinline__ uint32_t smem_u32(const void* p) {
    uint32_t a;
    asm("{ .reg .u64 t; cvta.to.shared.u64 t, %1; cvt.u32.u64 %0, t; }"
        : "=r"(a) : "l"(p));
    return a;
}

__device__ __forceinline__ uint32_t mapa_u32(uint32_t laddr, uint32_t rank) {
    uint32_t r;
    asm("mapa.shared::cluster.u32 %0, %1, %2;" : "=r"(r) : "r"(laddr), "r"(rank));
    return r;
}

__device__ __forceinline__ void st_cluster_f2(uint32_t addr, float2 v) {
    asm volatile("st.shared::cluster.v2.f32 [%0], {%1, %2};"
                 :: "r"(addr), "f"(v.x), "f"(v.y) : "memory");
}

__device__ __forceinline__ void cluster_sync_() {
    asm volatile("barrier.cluster.arrive.aligned;" ::: "memory");
    asm volatile("barrier.cluster.wait.aligned;" ::: "memory");
}

__device__ __forceinline__ uint32_t cta_rank_() {
    uint32_t r;
    asm("mov.u32 %0, %%cluster_ctarank;" : "=r"(r));
    return r;
}

// sigmoid / tanh via MUFU (__expf / __fdividef). Exact enough: rel_err ~1e-6.
__device__ __forceinline__ float sigf(float x) {
    return __fdividef(1.0f, 1.0f + __expf(-x));
}
__device__ __forceinline__ float tanhf_(float x) {
    return 2.0f * sigf(2.0f * x) - 1.0f;
}

extern __shared__ char smem_raw[];

__global__ __launch_bounds__(kThreads, 1) __cluster_dims__(8, 1, 1)
void lstm_persistent_kernel(const int*   __restrict__ tokens,   // [512,1024]
                            const float* __restrict__ Wx,       // [128,1024]
                            const float* __restrict__ Wh,       // [256,1024]
                            const float* __restrict__ bias,     // [1024]
                            const float* __restrict__ Wd,       // [256,128]
                            const float* __restrict__ bd,       // [128]
                            float*       __restrict__ out)      // [512,128]
{
    const int tid = threadIdx.x;
    const uint32_t rank = cta_rank_();
    const int bbase = (blockIdx.x >> 3) * 32;   // first batch of this cluster

    float* w_s = reinterpret_cast<float*>(smem_raw + W_OFF);
    int*  tok0 = reinterpret_cast<int*>(smem_raw + TOK_OFF);
    int*  tok1 = tok0 + 32;

    // ---- load W_h slice [k][c] (once) ----------------------------------
    for (int idx = tid; idx < 256 * 128; idx += kThreads) {
        int k = idx >> 7, c = idx & 127;
        int gcol = ((c >> 5) << 8) + (int)rank * 32 + (c & 31);
        w_s[idx] = Wh[k * 1024 + gcol];
    }
    // zero both h buffers
    {
        float2* h0 = reinterpret_cast<float2*>(smem_raw + H0_OFF);
        float2* h1 = reinterpret_cast<float2*>(smem_raw + H1_OFF);
        for (int i = tid; i < 256 * 16; i += kThreads) {
            h0[i] = make_float2(0.f, 0.f);
            h1[i] = make_float2(0.f, 0.f);
        }
    }

    // ---- gemv role: 1 column, 4 batch-pairs ------------------------------
    const int c  = tid & 127;            // local gate column 0..127
    const int ph = tid >> 7;             // 0..3 -> pairs 4ph..4ph+3
    const int gcol_t = ((c >> 5) << 8) + (int)rank * 32 + (c & 31);
    const float bias_c = bias[gcol_t];

    // ---- cell role: 1 (unit, pair) ---------------------------------------
    const int u_l = tid >> 4;            // 0..31
    const int pc  = tid & 15;            // pair 0..15
    const int ug  = (int)rank * 32 + u_l;
    float2 cst = make_float2(0.f, 0.f);

    const uint32_t my_base = smem_u32(smem_raw);
    uint32_t peer[8];
#pragma unroll
    for (int r = 0; r < 8; ++r) peer[r] = mapa_u32(my_base, (uint32_t)r);

    if (tid < 32) tok0[tid] = tokens[(bbase + tid) * kSeq];

    cluster_sync_();   // weights + zeroed h + tok0 visible cluster-wide

    uint32_t cur = H0_OFF, nxt = H1_OFF;

    for (int t = 0; t < kSeq; ++t) {
        const int* tokc = (t & 1) ? tok1 : tok0;
        if (tid < 32 && t + 1 < kSeq)
            ((t & 1) ? tok0 : tok1)[tid] = tokens[(bbase + tid) * kSeq + (t + 1)];

        // W_x gather for this thread's 8 batches (prefetched behind gemv)
        float wx[8];
#pragma unroll
        for (int j = 0; j < 8; ++j)
            wx[j] = Wx[tokc[8 * ph + j] * 1024 + gcol_t];

        // ---- gemv: acc[j] (+)= h[k][4ph+j] * w[k][c], packed f32x2 ------
        unsigned long long acc[4] = {0ull, 0ull, 0ull, 0ull};
        const char* hbase = smem_raw + cur + (uint32_t)(ph * 32);
#pragma unroll 8
        for (int k = 0; k < 256; ++k) {
            float w = w_s[(k << 7) + c];
            unsigned long long wp;
            asm("mov.b64 %0, {%1, %1};" : "=l"(wp) : "r"(__float_as_uint(w)));
            ulonglong2 h01 = *reinterpret_cast<const ulonglong2*>(hbase + k * 128);
            ulonglong2 h23 = *reinterpret_cast<const ulonglong2*>(hbase + k * 128 + 16);
            asm("fma.rn.f32x2 %0, %1, %2, %0;" : "+l"(acc[0]) : "l"(h01.x), "l"(wp));
            asm("fma.rn.f32x2 %0, %1, %2, %0;" : "+l"(acc[1]) : "l"(h01.y), "l"(wp));
            asm("fma.rn.f32x2 %0, %1, %2, %0;" : "+l"(acc[2]) : "l"(h23.x), "l"(wp));
            asm("fma.rn.f32x2 %0, %1, %2, %0;" : "+l"(acc[3]) : "l"(h23.y), "l"(wp));
        }

        // ---- gates (+Wx +bias) to SMEM: g[col][pair], stride 17 ----------
        {
            float2* g2 = reinterpret_cast<float2*>(smem_raw + G_OFF);
#pragma unroll
            for (int j = 0; j < 4; ++j) {
                float lo = __uint_as_float((uint32_t)acc[j]) + wx[2 * j] + bias_c;
                float hi = __uint_as_float((uint32_t)(acc[j] >> 32)) + wx[2 * j + 1] + bias_c;
                g2[c * G_STRIDE + 4 * ph + j] = make_float2(lo, hi);
            }
        }
        __syncthreads();

        // ---- LSTM cell + h broadcast to 8 cluster CTAs -------------------
        {
            const float2* g2 = reinterpret_cast<const float2*>(smem_raw + G_OFF);
            float2 gi = g2[(u_l     ) * G_STRIDE + pc];
            float2 gj = g2[(u_l + 32) * G_STRIDE + pc];
            float2 gf = g2[(u_l + 64) * G_STRIDE + pc];
            float2 go = g2[(u_l + 96) * G_STRIDE + pc];
            float cx = cst.x * sigf(gf.x + 1.0f) + sigf(gi.x) * tanhf_(gj.x);
            float cy = cst.y * sigf(gf.y + 1.0f) + sigf(gi.y) * tanhf_(gj.y);
            cst = make_float2(cx, cy);
            float2 hh = make_float2(tanhf_(cx) * sigf(go.x),
                                    tanhf_(cy) * sigf(go.y));
            uint32_t off = nxt + (uint32_t)((ug * 16 + pc) * 8);
#pragma unroll
            for (int r = 0; r < 8; ++r) st_cluster_f2(peer[r] + off, hh);
        }

        cluster_sync_();           // h(next) complete everywhere
        cur ^= H_XOR;
        nxt ^= H_XOR;
    }

    // ---- final dense: out[b,:] = h[b] @ W_dense + b_dense -----------------
    // rank r emits output columns [16r, 16r+16); W_d slice staged in SMEM.
    {
        float* wd_s = reinterpret_cast<float*>(smem_raw + G_OFF);  // 16KB
        for (int idx = tid; idx < 256 * 16; idx += kThreads)
            wd_s[idx] = Wd[(idx >> 4) * 128 + (int)rank * 16 + (idx & 15)];
        __syncthreads();

        const float* hf = reinterpret_cast<const float*>(smem_raw + cur);
        int coli = tid & 15;
        int b    = tid >> 4;                 // 0..31
        int colr = (int)rank * 16 + coli;
        float a = bd[colr];
#pragma unroll 8
        for (int k = 0; k < 256; ++k)
            a += hf[k * 32 + b] * wd_s[k * 16 + coli];
        out[(bbase + b) * 128 + colr] = a;
    }
}

extern "C" void kernel_launch(void* const* d_in, const int* in_sizes, int n_in,
                              void* d_out, int out_size) {
    (void)in_sizes; (void)n_in; (void)out_size;
    const int*   tokens = (const int*)d_in[0];
    const float* Wx     = (const float*)d_in[1];
    const float* Wh     = (const float*)d_in[2];
    const float* b      = (const float*)d_in[3];
    const float* Wd     = (const float*)d_in[4];
    const float* bd     = (const float*)d_in[5];
    float* out = (float*)d_out;

    cudaFuncSetAttribute(lstm_persistent_kernel,
                         cudaFuncAttributeMaxDynamicSharedMemorySize,
                         (int)SMEM_BYTES);

    // 16 clusters of 8 CTAs (static __cluster_dims__), 1 CTA/SM.
    lstm_persistent_kernel<<<128, kThreads, SMEM_BYTES>>>(
        tokens, Wx, Wh, b, Wd, bd, out);
}

// round 5
// speedup vs baseline: 1.1663x; 1.0001x over previous
#include <cuda_runtime.h>
#include <cstdint>

// ---------------------------------------------------------------------------
// Char-LSTM, 1024 steps, BATCH=512, UNITS=256, fp32 exact.
//
// 16 clusters x 8 CTAs (grid=128), 512 threads/CTA (16 warps, 1 CTA/SM).
//   cluster  -> 32 batches
//   CTA rank -> 32 units => 128 gate columns (i|j|f|o blocks of 32)
// W_h slice (256x128 fp32 = 128KB) SMEM-resident.
// Gemv thread: 1 column x 4 batch-pairs, packed fma.rn.f32x2 accumulators.
// Cell thread: 1 (unit, batch-pair); h broadcast to 8 cluster CTAs via
// st.shared::cluster into double-buffered h; one barrier.cluster per step.
// ---------------------------------------------------------------------------

namespace {
constexpr int kSeq     = 1024;
constexpr int kThreads = 512;

// shared memory map (bytes)
constexpr uint32_t W_OFF    = 0;                    // 256 x 128 fp32
constexpr uint32_t W_BYTES  = 256u * 128u * 4u;     // 131072
constexpr uint32_t H0_OFF   = W_OFF + W_BYTES;      // 131072
constexpr uint32_t H_BYTES  = 256u * 16u * 8u;      // 32768 : [k][pair] float2
constexpr uint32_t H1_OFF   = H0_OFF + H_BYTES;     // 163840
constexpr uint32_t H_XOR    = H0_OFF ^ H1_OFF;      // 0x8000
constexpr uint32_t G_OFF    = H1_OFF + H_BYTES;     // 196608
constexpr uint32_t G_STRIDE = 17;                   // float2 per column row (pad)
constexpr uint32_t G_BYTES  = 128u * G_STRIDE * 8u; // 17408
constexpr uint32_t TOK_OFF  = G_OFF + G_BYTES;      // 214016 : 2 x 32 int
constexpr uint32_t SMEM_BYTES = TOK_OFF + 2u * 32u * 4u;  // 214272
}  // namespace

__device__ __forceinline__ uint32_t smem_u32(const void* p) {
    uint32_t a;
    asm("{ .reg .u64 t; cvta.to.shared.u64 t, %1; cvt.u32.u64 %0, t; }"
        : "=r"(a) : "l"(p));
    return a;
}

__device__ __forceinline__ uint32_t mapa_u32(uint32_t laddr, uint32_t rank) {
    uint32_t r;
    asm("mapa.shared::cluster.u32 %0, %1, %2;" : "=r"(r) : "r"(laddr), "r"(rank));
    return r;
}

__device__ __forceinline__ void st_cluster_f2(uint32_t addr, float2 v) {
    asm volatile("st.shared::cluster.v2.f32 [%0], {%1, %2};"
                 :: "r"(addr), "f"(v.x), "f"(v.y) : "memory");
}

__device__ __forceinline__ void cluster_sync_() {
    asm volatile("barrier.cluster.arrive.aligned;" ::: "memory");
    asm volatile("barrier.cluster.wait.aligned;" ::: "memory");
}

__device__ __forceinline__ uint32_t cta_rank_() {
    uint32_t r;
    asm("mov.u32 %0, %%cluster_ctarank;" : "=r"(r));
    return r;
}

// sigmoid / tanh via MUFU (__expf / __fdividef). Exact enough: rel_err ~1e-6.
__device__ __forceinline__ float sigf(float x) {
    return __fdividef(1.0f, 1.0f + __expf(-x));
}
__device__ __forceinline__ float tanhf_(float x) {
    return 2.0f * sigf(2.0f * x) - 1.0f;
}

extern __shared__ char smem_raw[];

__global__ __launch_bounds__(kThreads, 1) __cluster_dims__(8, 1, 1)
void lstm_persistent_kernel(const int*   __restrict__ tokens,   // [512,1024]
                            const float* __restrict__ Wx,       // [128,1024]
                            const float* __restrict__ Wh,       // [256,1024]
                            const float* __restrict__ bias,     // [1024]
                            const float* __restrict__ Wd,       // [256,128]
                            const float* __restrict__ bd,       // [128]
                            float*       __restrict__ out)      // [512,128]
{
    const int tid = threadIdx.x;
    const uint32_t rank = cta_rank_();
    const int bbase = (blockIdx.x >> 3) * 32;   // first batch of this cluster

    float* w_s = reinterpret_cast<float*>(smem_raw + W_OFF);
    int*  tok0 = reinterpret_cast<int*>(smem_raw + TOK_OFF);
    int*  tok1 = tok0 + 32;

    // ---- load W_h slice [k][c] (once) ----------------------------------
    for (int idx = tid; idx < 256 * 128; idx += kThreads) {
        int k = idx >> 7, c = idx & 127;
        int gcol = ((c >> 5) << 8) + (int)rank * 32 + (c & 31);
        w_s[idx] = Wh[k * 1024 + gcol];
    }
    // zero both h buffers
    {
        float2* h0 = reinterpret_cast<float2*>(smem_raw + H0_OFF);
        float2* h1 = reinterpret_cast<float2*>(smem_raw + H1_OFF);
        for (int i = tid; i < 256 * 16; i += kThreads) {
            h0[i] = make_float2(0.f, 0.f);
            h1[i] = make_float2(0.f, 0.f);
        }
    }

    // ---- gemv role: 1 column, 4 batch-pairs ------------------------------
    const int c  = tid & 127;            // local gate column 0..127
    const int ph = tid >> 7;             // 0..3 -> pairs 4ph..4ph+3
    const int gcol_t = ((c >> 5) << 8) + (int)rank * 32 + (c & 31);
    const float bias_c = bias[gcol_t];

    // ---- cell role: 1 (unit, pair) ---------------------------------------
    const int u_l = tid >> 4;            // 0..31
    const int pc  = tid & 15;            // pair 0..15
    const int ug  = (int)rank * 32 + u_l;
    float2 cst = make_float2(0.f, 0.f);

    const uint32_t my_base = smem_u32(smem_raw);
    uint32_t peer[8];
#pragma unroll
    for (int r = 0; r < 8; ++r) peer[r] = mapa_u32(my_base, (uint32_t)r);

    if (tid < 32) tok0[tid] = tokens[(bbase + tid) * kSeq];

    cluster_sync_();   // weights + zeroed h + tok0 visible cluster-wide

    uint32_t cur = H0_OFF, nxt = H1_OFF;

    for (int t = 0; t < kSeq; ++t) {
        const int* tokc = (t & 1) ? tok1 : tok0;
        if (tid < 32 && t + 1 < kSeq)
            ((t & 1) ? tok0 : tok1)[tid] = tokens[(bbase + tid) * kSeq + (t + 1)];

        // W_x gather for this thread's 8 batches (prefetched behind gemv)
        float wx[8];
#pragma unroll
        for (int j = 0; j < 8; ++j)
            wx[j] = Wx[tokc[8 * ph + j] * 1024 + gcol_t];

        // ---- gemv: acc[j] (+)= h[k][4ph+j] * w[k][c], packed f32x2 ------
        unsigned long long acc[4] = {0ull, 0ull, 0ull, 0ull};
        const char* hbase = smem_raw + cur + (uint32_t)(ph * 32);
#pragma unroll 8
        for (int k = 0; k < 256; ++k) {
            float w = w_s[(k << 7) + c];
            unsigned long long wp;
            asm("mov.b64 %0, {%1, %1};" : "=l"(wp) : "r"(__float_as_uint(w)));
            ulonglong2 h01 = *reinterpret_cast<const ulonglong2*>(hbase + k * 128);
            ulonglong2 h23 = *reinterpret_cast<const ulonglong2*>(hbase + k * 128 + 16);
            asm("fma.rn.f32x2 %0, %1, %2, %0;" : "+l"(acc[0]) : "l"(h01.x), "l"(wp));
            asm("fma.rn.f32x2 %0, %1, %2, %0;" : "+l"(acc[1]) : "l"(h01.y), "l"(wp));
            asm("fma.rn.f32x2 %0, %1, %2, %0;" : "+l"(acc[2]) : "l"(h23.x), "l"(wp));
            asm("fma.rn.f32x2 %0, %1, %2, %0;" : "+l"(acc[3]) : "l"(h23.y), "l"(wp));
        }

        // ---- gates (+Wx +bias) to SMEM: g[col][pair], stride 17 ----------
        {
            float2* g2 = reinterpret_cast<float2*>(smem_raw + G_OFF);
#pragma unroll
            for (int j = 0; j < 4; ++j) {
                float lo = __uint_as_float((uint32_t)acc[j]) + wx[2 * j] + bias_c;
                float hi = __uint_as_float((uint32_t)(acc[j] >> 32)) + wx[2 * j + 1] + bias_c;
                g2[c * G_STRIDE + 4 * ph + j] = make_float2(lo, hi);
            }
        }
        __syncthreads();

        // ---- LSTM cell + h broadcast to 8 cluster CTAs -------------------
        {
            const float2* g2 = reinterpret_cast<const float2*>(smem_raw + G_OFF);
            float2 gi = g2[(u_l     ) * G_STRIDE + pc];
            float2 gj = g2[(u_l + 32) * G_STRIDE + pc];
            float2 gf = g2[(u_l + 64) * G_STRIDE + pc];
            float2 go = g2[(u_l + 96) * G_STRIDE + pc];
            float cx = cst.x * sigf(gf.x + 1.0f) + sigf(gi.x) * tanhf_(gj.x);
            float cy = cst.y * sigf(gf.y + 1.0f) + sigf(gi.y) * tanhf_(gj.y);
            cst = make_float2(cx, cy);
            float2 hh = make_float2(tanhf_(cx) * sigf(go.x),
                                    tanhf_(cy) * sigf(go.y));
            uint32_t off = nxt + (uint32_t)((ug * 16 + pc) * 8);
#pragma unroll
            for (int r = 0; r < 8; ++r) st_cluster_f2(peer[r] + off, hh);
        }

        cluster_sync_();           // h(next) complete everywhere
        cur ^= H_XOR;
        nxt ^= H_XOR;
    }

    // ---- final dense: out[b,:] = h[b] @ W_dense + b_dense -----------------
    // rank r emits output columns [16r, 16r+16); W_d slice staged in SMEM.
    {
        float* wd_s = reinterpret_cast<float*>(smem_raw + G_OFF);  // 16KB
        for (int idx = tid; idx < 256 * 16; idx += kThreads)
            wd_s[idx] = Wd[(idx >> 4) * 128 + (int)rank * 16 + (idx & 15)];
        __syncthreads();

        const float* hf = reinterpret_cast<const float*>(smem_raw + cur);
        int coli = tid & 15;
        int b    = tid >> 4;                 // 0..31
        int colr = (int)rank * 16 + coli;
        float a = bd[colr];
#pragma unroll 8
        for (int k = 0; k < 256; ++k)
            a += hf[k * 32 + b] * wd_s[k * 16 + coli];
        out[(bbase + b) * 128 + colr] = a;
    }
}

extern "C" void kernel_launch(void* const* d_in, const int* in_sizes, int n_in,
                              void* d_out, int out_size) {
    (void)in_sizes; (void)n_in; (void)out_size;
    const int*   tokens = (const int*)d_in[0];
    const float* Wx     = (const float*)d_in[1];
    const float* Wh     = (const float*)d_in[2];
    const float* b      = (const float*)d_in[3];
    const float* Wd     = (const float*)d_in[4];
    const float* bd     = (const float*)d_in[5];
    float* out = (float*)d_out;

    cudaFuncSetAttribute(lstm_persistent_kernel,
                         cudaFuncAttributeMaxDynamicSharedMemorySize,
                         (int)SMEM_BYTES);

    // 16 clusters of 8 CTAs (static __cluster_dims__), 1 CTA/SM.
    lstm_persistent_kernel<<<128, kThreads, SMEM_BYTES>>>(
        tokens, Wx, Wh, b, Wd, bd, out);
}

// round 7
// speedup vs baseline: 3.0608x; 2.6244x over previous
#include <cuda_runtime.h>
#include <cuda_fp16.h>
#include <cstdint>

// ---------------------------------------------------------------------------
// Char-LSTM via warp-level mma.sync (HMMA, fp16 hi/lo split), 1024 steps,
// BATCH=512, UNITS=256. tcgen05 unavailable (harness compiles compute_103
// virtual arch -> arch-specific instrs rejected), so use baseline-PTX tensor
// path: ldmatrix + mma.sync.m16n8k16.
//
// 16 clusters x 8 CTAs (grid=128), 512 thr/CTA, 1 CTA/SM.
//   cluster -> 32 batches; CTA rank r -> 32 units = 128 gate cols.
// W_h slice as fp16 hi/lo B-fragments, REGISTER-resident (64 regs/warp).
// A = h (32 x 256) fp16 hi/lo in SMEM staging (double-buffered); lo scaled
// x64 to stay fp16-normal. gates = Ahi*Whi + (Alo*Whi + Ahi*Wlo)/64.
// Cell -> h hi/lo -> DSMEM broadcast to 8 CTAs -> barrier.cluster per step.
// ---------------------------------------------------------------------------

namespace {
constexpr int kSeq     = 1024;
constexpr int kThreads = 512;
constexpr float kScale = 64.0f;
constexpr float kInv   = 1.0f / 64.0f;

// A staging: [batch 0..31][k 0..263] fp16, row stride 528 B (16B aligned,
// 132 words == 4 mod 32 banks -> ldmatrix conflict-free).
constexpr uint32_t A_STRIDE = 528;
constexpr uint32_t A_SIZE   = 32u * A_STRIDE;          // 16896
constexpr uint32_t AHI0 = 0;
constexpr uint32_t ALO0 = AHI0 + A_SIZE;               // 16896
constexpr uint32_t AHI1 = ALO0 + A_SIZE;               // 33792
constexpr uint32_t BUF_STRIDE = AHI1;                  // 33792 (buf0->buf1)
constexpr uint32_t GATES = AHI1 + 2u * A_SIZE;         // 67584: [b][132] f32
constexpr uint32_t GATES_SIZE = 32u * 132u * 4u;       // 16896
constexpr uint32_t TOK = GATES + GATES_SIZE;           // 84480: 2 x 32 int
constexpr uint32_t SMEM_BYTES = TOK + 256;             // 84736
}  // namespace

// ---------------- PTX helpers ----------------------------------------------
__device__ __forceinline__ uint32_t smem_u32(const void* p) {
    uint32_t a;
    asm("{ .reg .u64 t; cvta.to.shared.u64 t, %1; cvt.u32.u64 %0, t; }" : "=r"(a) : "l"(p));
    return a;
}
__device__ __forceinline__ uint32_t mapa_u32(uint32_t a, uint32_t r) {
    uint32_t o;
    asm("mapa.shared::cluster.u32 %0, %1, %2;" : "=r"(o) : "r"(a), "r"(r));
    return o;
}
__device__ __forceinline__ void st_cluster_u32(uint32_t a, uint32_t v) {
    asm volatile("st.shared::cluster.u32 [%0], %1;" :: "r"(a), "r"(v) : "memory");
}
__device__ __forceinline__ void cluster_sync_() {
    asm volatile("barrier.cluster.arrive.aligned;" ::: "memory");
    asm volatile("barrier.cluster.wait.aligned;" ::: "memory");
}
__device__ __forceinline__ uint32_t cta_rank_() {
    uint32_t r; asm("mov.u32 %0, %%cluster_ctarank;" : "=r"(r)); return r;
}
__device__ __forceinline__ void ldsm_x4_(uint32_t* r, uint32_t addr) {
    asm volatile("ldmatrix.sync.aligned.m8n8.x4.shared.b16 {%0,%1,%2,%3}, [%4];"
                 : "=r"(r[0]), "=r"(r[1]), "=r"(r[2]), "=r"(r[3]) : "r"(addr));
}
__device__ __forceinline__ void mma16816_(float* d, const uint32_t* a,
                                          uint32_t b0, uint32_t b1) {
    asm volatile(
        "mma.sync.aligned.m16n8k16.row.col.f32.f16.f16.f32 "
        "{%0,%1,%2,%3}, {%4,%5,%6,%7}, {%8,%9}, {%0,%1,%2,%3};"
        : "+f"(d[0]), "+f"(d[1]), "+f"(d[2]), "+f"(d[3])
        : "r"(a[0]), "r"(a[1]), "r"(a[2]), "r"(a[3]), "r"(b0), "r"(b1));
}
__device__ __forceinline__ void st_v2_(uint32_t addr, float x, float y) {
    asm volatile("st.shared.v2.f32 [%0], {%1, %2};" :: "r"(addr), "f"(x), "f"(y) : "memory");
}
__device__ __forceinline__ float sigf(float x) {
    return __fdividef(1.0f, 1.0f + __expf(-x));
}
__device__ __forceinline__ float tanhf_(float x) { return 2.0f * sigf(2.0f * x) - 1.0f; }

// pack two floats as fp16 pair (low half = first element)
__device__ __forceinline__ uint32_t pack2h(float a, float b) {
    __half2 h = __floats2half2_rn(a, b);
    return *reinterpret_cast<uint32_t*>(&h);
}

extern __shared__ char smem_raw[];

__global__ __launch_bounds__(kThreads, 1) __cluster_dims__(8, 1, 1)
void lstm_hmma_kernel(const int*   __restrict__ tokens,  // [512,1024]
                      const float* __restrict__ Wx,      // [128,1024]
                      const float* __restrict__ Wh,      // [256,1024]
                      const float* __restrict__ bias,    // [1024]
                      const float* __restrict__ Wd,      // [256,128]
                      const float* __restrict__ bd,      // [128]
                      float*       __restrict__ out)     // [512,128]
{
    const int tid  = threadIdx.x;
    const int lane = tid & 31;
    const int warp = tid >> 5;                 // 0..15, owns local cols 8w..8w+7
    const uint32_t rank = cta_rank_();
    const int bbase = (blockIdx.x >> 3) * 32;
    const uint32_t sbase = smem_u32(smem_raw);
    int* tk = reinterpret_cast<int*>(smem_raw + TOK);

    // ---- zero A buf0 (hi+lo) ---------------------------------------------
    for (int i = tid; i < (int)(2 * A_SIZE / 4); i += kThreads)
        reinterpret_cast<uint32_t*>(smem_raw)[i] = 0;

    // ---- W_h B-fragments (register-resident, hi/lo, lo scaled x64) -------
    // lane's col: n = 8*warp + (lane>>2); global col = (n>>5)*256 + rank*32 + (n&31)
    uint32_t wh[32], wl[32];
    {
        int n = warp * 8 + (lane >> 2);
        int gc = ((n >> 5) << 8) + (int)rank * 32 + (n & 31);
#pragma unroll
        for (int kt = 0; kt < 16; ++kt) {
            int k0 = kt * 16 + (lane & 3) * 2;
#pragma unroll
            for (int j = 0; j < 2; ++j) {           // j=0: k0, j=1: k0+8
                float w0 = Wh[(k0 + 8 * j) * 1024 + gc];
                float w1 = Wh[(k0 + 8 * j + 1) * 1024 + gc];
                float h0 = __half2float(__float2half_rn(w0));
                float h1 = __half2float(__float2half_rn(w1));
                wh[kt * 2 + j] = pack2h(h0, h1);
                wl[kt * 2 + j] = pack2h((w0 - h0) * kScale, (w1 - h1) * kScale);
            }
        }
    }

    // bias for gemm store (cols n0, n0+1)
    const int ncol0 = warp * 8 + (lane & 3) * 2;
    float bias0, bias1;
    {
        int g0 = ((ncol0 >> 5) << 8) + (int)rank * 32 + (ncol0 & 31);
        bias0 = bias[g0];
        bias1 = bias[g0 + 1];
    }

    // ldmatrix per-lane address offset (within an A array)
    // group g = lane>>3: row = (g&1)*8 + (lane&7), kbyte = (g>>1)*16
    const uint32_t aoff =
        (uint32_t)((((lane >> 3) & 1) * 8 + (lane & 7)) * A_STRIDE +
                   ((lane >> 4) & 1) * 16);

    // cell role: batch cb, unit-pair cu (units 2cu, 2cu+1 of this CTA)
    const int cb = tid >> 4;      // 0..31
    const int cu = tid & 15;      // 0..15
    float c0 = 0.f, c1 = 0.f;
    const uint32_t hOffBase =
        (uint32_t)(cb * (int)A_STRIDE + ((int)rank * 32 + 2 * cu) * 2);

    uint32_t peer[8];
#pragma unroll
    for (int r = 0; r < 8; ++r) peer[r] = mapa_u32(sbase, (uint32_t)r);

    if (tid < 32) tk[tid] = tokens[(bbase + tid) * kSeq];
    __syncthreads();
    cluster_sync_();

    const uint32_t gatesBase = sbase + GATES;

    for (int t = 0; t < kSeq; ++t) {
        const uint32_t rOff = (t & 1) ? BUF_STRIDE : 0u;
        const uint32_t wOff = rOff ^ BUF_STRIDE;

        // ---- prefetch Wx gather + next tokens (hidden behind gemm) ------
        int tok_b = tk[(t & 1) * 32 + cb];
        const float* wxp = Wx + tok_b * 1024 + (int)rank * 32 + 2 * cu;
        float2 wx0 = *reinterpret_cast<const float2*>(wxp);
        float2 wx1 = *reinterpret_cast<const float2*>(wxp + 256);
        float2 wx2 = *reinterpret_cast<const float2*>(wxp + 512);
        float2 wx3 = *reinterpret_cast<const float2*>(wxp + 768);
        if (tid < 32 && t + 1 < kSeq)
            tk[((t + 1) & 1) * 32 + tid] = tokens[(bbase + tid) * kSeq + (t + 1)];

        // ---- gemm: 16 k-tiles, 2 m-tiles, n=8 per warp --------------------
        float aA0[4] = {0.f, 0.f, 0.f, 0.f};   // m-tile0, hi*Whi
        float aB0[4] = {0.f, 0.f, 0.f, 0.f};   // m-tile0, lo-terms (x64)
        float aA1[4] = {0.f, 0.f, 0.f, 0.f};
        float aB1[4] = {0.f, 0.f, 0.f, 0.f};
        const uint32_t hiB = sbase + rOff + aoff;
        const uint32_t loB = hiB + A_SIZE;
#pragma unroll
        for (int kt = 0; kt < 16; ++kt) {
            const uint32_t ko = (uint32_t)(kt * 32);
            uint32_t ah0[4], ah1[4], al0[4], al1[4];
            ldsm_x4_(ah0, hiB + ko);
            ldsm_x4_(ah1, hiB + ko + 16u * A_STRIDE);
            ldsm_x4_(al0, loB + ko);
            ldsm_x4_(al1, loB + ko + 16u * A_STRIDE);
            mma16816_(aA0, ah0, wh[2 * kt], wh[2 * kt + 1]);
            mma16816_(aB0, al0, wh[2 * kt], wh[2 * kt + 1]);
            mma16816_(aB0, ah0, wl[2 * kt], wl[2 * kt + 1]);
            mma16816_(aA1, ah1, wh[2 * kt], wh[2 * kt + 1]);
            mma16816_(aB1, al1, wh[2 * kt], wh[2 * kt + 1]);
            mma16816_(aB1, ah1, wl[2 * kt], wl[2 * kt + 1]);
        }

        // ---- store gates[b][col] = acc + lo/64 + bias ---------------------
        {
            int r0 = lane >> 2;
            uint32_t base = gatesBase + (uint32_t)(ncol0 * 4);
            st_v2_(base + (uint32_t)((r0     ) * 528),
                   fmaf(aB0[0], kInv, aA0[0]) + bias0,
                   fmaf(aB0[1], kInv, aA0[1]) + bias1);
            st_v2_(base + (uint32_t)((r0 +  8) * 528),
                   fmaf(aB0[2], kInv, aA0[2]) + bias0,
                   fmaf(aB0[3], kInv, aA0[3]) + bias1);
            st_v2_(base + (uint32_t)((r0 + 16) * 528),
                   fmaf(aB1[0], kInv, aA1[0]) + bias0,
                   fmaf(aB1[1], kInv, aA1[1]) + bias1);
            st_v2_(base + (uint32_t)((r0 + 24) * 528),
                   fmaf(aB1[2], kInv, aA1[2]) + bias0,
                   fmaf(aB1[3], kInv, aA1[3]) + bias1);
        }
        __syncthreads();

        // ---- LSTM cell (2 units x 1 batch per thread) ---------------------
        float hv[2];
        {
            const float* gp = reinterpret_cast<const float*>(smem_raw + GATES) + cb * 132;
#pragma unroll
            for (int q = 0; q < 2; ++q) {
                int lc = 2 * cu + q;
                float gi = gp[lc      ] + (q ? wx0.y : wx0.x);
                float gj = gp[lc +  32] + (q ? wx1.y : wx1.x);
                float gf = gp[lc +  64] + (q ? wx2.y : wx2.x);
                float go = gp[lc +  96] + (q ? wx3.y : wx3.x);
                float& cs = q ? c1 : c0;
                cs = cs * sigf(gf + 1.0f) + sigf(gi) * tanhf_(gj);
                hv[q] = tanhf_(cs) * sigf(go);
            }
        }
        // pack hi / scaled-lo for the two units, broadcast to 8 CTAs
        {
            float h0 = __half2float(__float2half_rn(hv[0]));
            float h1 = __half2float(__float2half_rn(hv[1]));
            uint32_t whi = pack2h(h0, h1);
            uint32_t wlo = pack2h((hv[0] - h0) * kScale, (hv[1] - h1) * kScale);
            uint32_t offH = wOff + hOffBase;
            uint32_t offL = offH + A_SIZE;
#pragma unroll
            for (int r = 0; r < 8; ++r) {
                st_cluster_u32(peer[r] + offH, whi);
                st_cluster_u32(peer[r] + offL, wlo);
            }
        }
        cluster_sync_();
    }

    // ---- dense epilogue: out[b,:] = h @ Wd + bd ---------------------------
    // final h in buf0 (t=1023 wrote wOff=0). rank r -> out cols [16r,16r+16).
    {
        float* wds = reinterpret_cast<float*>(smem_raw + GATES);
        for (int idx = tid; idx < 256 * 16; idx += kThreads)
            wds[idx] = Wd[(idx >> 4) * 128 + (int)rank * 16 + (idx & 15)];
        __syncthreads();

        const __half* hh = reinterpret_cast<const __half*>(smem_raw + AHI0);
        const __half* hl = reinterpret_cast<const __half*>(smem_raw + ALO0);
        int coli = tid & 15, bb = tid >> 4;
        int colr = (int)rank * 16 + coli;
        float acc = bd[colr];
        int rowo = bb * 264;
#pragma unroll 8
        for (int u = 0; u < 256; ++u) {
            float h = __half2float(hh[rowo + u]) + __half2float(hl[rowo + u]) * kInv;
            acc += h * wds[u * 16 + coli];
        }
        out[(bbase + bb) * 128 + colr] = acc;
    }
}

extern "C" void kernel_launch(void* const* d_in, const int* in_sizes, int n_in,
                              void* d_out, int out_size) {
    (void)in_sizes; (void)n_in; (void)out_size;
    const int*   tokens = (const int*)d_in[0];
    const float* Wx     = (const float*)d_in[1];
    const float* Wh     = (const float*)d_in[2];
    const float* b      = (const float*)d_in[3];
    const float* Wd     = (const float*)d_in[4];
    const float* bd     = (const float*)d_in[5];
    float* out = (float*)d_out;

    cudaFuncSetAttribute(lstm_hmma_kernel,
                         cudaFuncAttributeMaxDynamicSharedMemorySize,
                         (int)SMEM_BYTES);
    lstm_hmma_kernel<<<128, kThreads, SMEM_BYTES>>>(tokens, Wx, Wh, b, Wd, bd, out);
}